// round 8
// baseline (speedup 1.0000x reference)
#include <cuda_runtime.h>

// B_Splines fused: out[i][j] = spline(x[i]; coefs) * spline(t[j]; coefs_2)
// degree P=3, N_COEFS=128, knots[132] open-uniform on [0,1], h = 1/125.
//
// R7-best config (64x1024 tiles, 1024 CTAs = one resident wave, SMEM row
// cache + one barrier, division-free Cox-de Boor) with ONE change:
// __stwt write-through stores. Rationale: ncu byte balance shows ~60MB of
// the 268MB output still dirty in L2 at kernel retire (4537GB/s x 45.8us =
// 207MB counted); that flush tail serializes into the replay period.
// Write-through drains to DRAM in-flight; stores are perfectly coalesced
// full-line writes, the best case for wt.
//
// Inputs (metadata order): x[8192], t[8192], knots[132], coefs[128], coefs_2[128]
// Output: float32 [8192, 8192]

#define NX 8192
#define NT 8192

#define TPB 256
#define ROWS_PER_BLOCK 64
#define COLS_PER_BLOCK (TPB * 4)   // 1024

__device__ __forceinline__ int clampi(int i) {
    return min(max(i, 3), 128);
}

// reciprocal of (n * h), n in {1,2,3}, h = 1/125 (open-uniform closed form)
__device__ __forceinline__ float recip_n(int n) {
    return n == 1 ? 125.0f : (n == 2 ? 62.5f : 41.666668f);
}

__device__ __forceinline__ float rden(int k, int a, int b) {
    return recip_n(clampi(k + a) - clampi(k + b));
}

__device__ __forceinline__ float spline_eval(float xv,
                                             const float* __restrict__ knots,
                                             const float* __restrict__ c) {
    // Knot span: uniform interior gives the guess; local fix against actual
    // fp32 knots keeps indicator parity (t[k] <= x < t[k+1]).
    int k = 3 + (int)floorf(xv * 125.0f);
    k = max(3, min(127, k));
    while (k > 3   && xv <  __ldg(knots + k))     k--;
    while (k < 127 && xv >= __ldg(knots + k + 1)) k++;

    float tm2 = __ldg(knots + k - 2);
    float tm1 = __ldg(knots + k - 1);
    float t0  = __ldg(knots + k);
    float t1  = __ldg(knots + k + 1);
    float t2  = __ldg(knots + k + 2);
    float t3  = __ldg(knots + k + 3);

    float l1 = xv - t0,  r1 = t1 - xv;
    float l2 = xv - tm1, r2 = t2 - xv;
    float l3 = xv - tm2, r3 = t3 - xv;

    // Triangular algorithm (NURBS A2.2), closed-form denominators.
    float N0, N1, N2, N3, temp, saved;
    temp = rden(k, 1, 0);
    N1 = l1 * temp;
    N0 = r1 * temp;
    temp  = N0 * rden(k, 1, -1);
    N0    = r1 * temp;
    saved = l2 * temp;
    temp  = N1 * rden(k, 2, 0);
    N1    = saved + r2 * temp;
    N2    = l1 * temp;
    temp  = N0 * rden(k, 1, -2);
    N0    = r1 * temp;
    saved = l3 * temp;
    temp  = N1 * rden(k, 2, -1);
    N1    = saved + r2 * temp;
    saved = l2 * temp;
    temp  = N2 * rden(k, 3, 0);
    N2    = saved + r3 * temp;
    N3    = l1 * temp;

    return __ldg(c + k - 3) * N0 + __ldg(c + k - 2) * N1 +
           __ldg(c + k - 1) * N2 + __ldg(c + k)     * N3;
}

__global__ __launch_bounds__(TPB, 8) void bspline_outer_fused(
    const float* __restrict__ x,
    const float* __restrict__ t,
    const float* __restrict__ knots,
    const float* __restrict__ coefs,
    const float* __restrict__ coefs2,
    float* __restrict__ out) {
    __shared__ float s_sx[ROWS_PER_BLOCK];

    const int tid = threadIdx.x;
    const int j   = blockIdx.x * COLS_PER_BLOCK + tid * 4;  // base column
    const int r0  = blockIdx.y * ROWS_PER_BLOCK;            // base row

    // Row spline values -> SMEM (threads 0..63).
    if (tid < ROWS_PER_BLOCK) {
        s_sx[tid] = spline_eval(__ldg(x + r0 + tid), knots, coefs);
    }

    // Column spline values for this thread's 4 columns (independent -> ILP).
    float4 tv = *reinterpret_cast<const float4*>(t + j);
    float4 s4;
    s4.x = spline_eval(tv.x, knots, coefs2);
    s4.y = spline_eval(tv.y, knots, coefs2);
    s4.z = spline_eval(tv.z, knots, coefs2);
    s4.w = spline_eval(tv.w, knots, coefs2);

    __syncthreads();

    // Store drain: 64 rows x 16B per thread, fully coalesced, write-through.
    float4* outp = reinterpret_cast<float4*>(out + (size_t)r0 * NT + j);
#pragma unroll 16
    for (int r = 0; r < ROWS_PER_BLOCK; r++) {
        float a = s_sx[r];
        float4 o;
        o.x = a * s4.x;
        o.y = a * s4.y;
        o.z = a * s4.z;
        o.w = a * s4.w;
        __stwt(outp, o);
        outp += NT / 4;
    }
}

extern "C" void kernel_launch(void* const* d_in, const int* in_sizes, int n_in,
                              void* d_out, int out_size) {
    const float* x      = (const float*)d_in[0];
    const float* t      = (const float*)d_in[1];
    const float* knots  = (const float*)d_in[2];
    const float* coefs  = (const float*)d_in[3];
    const float* coefs2 = (const float*)d_in[4];
    float* out = (float*)d_out;

    dim3 grid(NT / COLS_PER_BLOCK, NX / ROWS_PER_BLOCK);  // (8, 128)
    bspline_outer_fused<<<grid, TPB>>>(x, t, knots, coefs, coefs2, out);
}

// round 9
// speedup vs baseline: 1.3034x; 1.3034x over previous
#include <cuda_runtime.h>

// B_Splines fused: out[i][j] = spline(x[i]; coefs) * spline(t[j]; coefs_2)
// degree P=3, N_COEFS=128, knots[132] open-uniform on [0,1], h = 1/125.
//
// R7-best geometry (64-row x 1024-col tiles, 1024 CTAs = one resident wave,
// SMEM row cache + one barrier, division-free Cox-de Boor, evict-streaming
// stores) with Blackwell 256-bit stores: TPB=128, each thread owns 8
// contiguous floats -> one st.global.cs.v8.f32 per row (half the STG count
// and L1tex wavefronts per byte vs STG.128).
// NOTE (R8): __stwt write-through measured 66us (LTS sector serialization) —
// do not revisit. In-kernel write rate at R7 was already 5.87 TB/s.
//
// Inputs (metadata order): x[8192], t[8192], knots[132], coefs[128], coefs_2[128]
// Output: float32 [8192, 8192]

#define NX 8192
#define NT 8192

#define TPB 128
#define ROWS_PER_BLOCK 64
#define COLS_PER_BLOCK 1024        // TPB * 8

__device__ __forceinline__ int clampi(int i) {
    return min(max(i, 3), 128);
}

// reciprocal of (n * h), n in {1,2,3}, h = 1/125 (open-uniform closed form)
__device__ __forceinline__ float recip_n(int n) {
    return n == 1 ? 125.0f : (n == 2 ? 62.5f : 41.666668f);
}

__device__ __forceinline__ float rden(int k, int a, int b) {
    return recip_n(clampi(k + a) - clampi(k + b));
}

__device__ __forceinline__ float spline_eval(float xv,
                                             const float* __restrict__ knots,
                                             const float* __restrict__ c) {
    // Knot span: uniform interior gives the guess; local fix against actual
    // fp32 knots keeps indicator parity (t[k] <= x < t[k+1]).
    int k = 3 + (int)floorf(xv * 125.0f);
    k = max(3, min(127, k));
    while (k > 3   && xv <  __ldg(knots + k))     k--;
    while (k < 127 && xv >= __ldg(knots + k + 1)) k++;

    float tm2 = __ldg(knots + k - 2);
    float tm1 = __ldg(knots + k - 1);
    float t0  = __ldg(knots + k);
    float t1  = __ldg(knots + k + 1);
    float t2  = __ldg(knots + k + 2);
    float t3  = __ldg(knots + k + 3);

    float l1 = xv - t0,  r1 = t1 - xv;
    float l2 = xv - tm1, r2 = t2 - xv;
    float l3 = xv - tm2, r3 = t3 - xv;

    // Triangular algorithm (NURBS A2.2), closed-form denominators.
    float N0, N1, N2, N3, temp, saved;
    temp = rden(k, 1, 0);
    N1 = l1 * temp;
    N0 = r1 * temp;
    temp  = N0 * rden(k, 1, -1);
    N0    = r1 * temp;
    saved = l2 * temp;
    temp  = N1 * rden(k, 2, 0);
    N1    = saved + r2 * temp;
    N2    = l1 * temp;
    temp  = N0 * rden(k, 1, -2);
    N0    = r1 * temp;
    saved = l3 * temp;
    temp  = N1 * rden(k, 2, -1);
    N1    = saved + r2 * temp;
    saved = l2 * temp;
    temp  = N2 * rden(k, 3, 0);
    N2    = saved + r3 * temp;
    N3    = l1 * temp;

    return __ldg(c + k - 3) * N0 + __ldg(c + k - 2) * N1 +
           __ldg(c + k - 1) * N2 + __ldg(c + k)     * N3;
}

// 256-bit streaming store (Blackwell STG.E.256, evict-streaming).
__device__ __forceinline__ void stg256_cs(float* p,
                                          float a0, float a1, float a2, float a3,
                                          float a4, float a5, float a6, float a7) {
    asm volatile(
        "st.global.cs.v8.f32 [%0], {%1,%2,%3,%4,%5,%6,%7,%8};"
        :: "l"(p), "f"(a0), "f"(a1), "f"(a2), "f"(a3),
                   "f"(a4), "f"(a5), "f"(a6), "f"(a7)
        : "memory");
}

__global__ __launch_bounds__(TPB, 16) void bspline_outer_fused(
    const float* __restrict__ x,
    const float* __restrict__ t,
    const float* __restrict__ knots,
    const float* __restrict__ coefs,
    const float* __restrict__ coefs2,
    float* __restrict__ out) {
    __shared__ float s_sx[ROWS_PER_BLOCK];

    const int tid = threadIdx.x;
    const int j   = blockIdx.x * COLS_PER_BLOCK + tid * 8;  // base column (8 floats)
    const int r0  = blockIdx.y * ROWS_PER_BLOCK;            // base row

    // Row spline values -> SMEM (threads 0..63).
    if (tid < ROWS_PER_BLOCK) {
        s_sx[tid] = spline_eval(__ldg(x + r0 + tid), knots, coefs);
    }

    // Column spline values for this thread's 8 columns (independent -> ILP).
    float4 tva = *reinterpret_cast<const float4*>(t + j);
    float4 tvb = *reinterpret_cast<const float4*>(t + j + 4);
    float s0 = spline_eval(tva.x, knots, coefs2);
    float s1 = spline_eval(tva.y, knots, coefs2);
    float s2 = spline_eval(tva.z, knots, coefs2);
    float s3 = spline_eval(tva.w, knots, coefs2);
    float s4 = spline_eval(tvb.x, knots, coefs2);
    float s5 = spline_eval(tvb.y, knots, coefs2);
    float s6 = spline_eval(tvb.z, knots, coefs2);
    float s7 = spline_eval(tvb.w, knots, coefs2);

    __syncthreads();

    // Store drain: 64 rows x one 32B STG.256 per thread, fully coalesced.
    float* outp = out + (size_t)r0 * NT + j;
#pragma unroll 16
    for (int r = 0; r < ROWS_PER_BLOCK; r++) {
        float a = s_sx[r];
        stg256_cs(outp, a * s0, a * s1, a * s2, a * s3,
                        a * s4, a * s5, a * s6, a * s7);
        outp += NT;
    }
}

extern "C" void kernel_launch(void* const* d_in, const int* in_sizes, int n_in,
                              void* d_out, int out_size) {
    const float* x      = (const float*)d_in[0];
    const float* t      = (const float*)d_in[1];
    const float* knots  = (const float*)d_in[2];
    const float* coefs  = (const float*)d_in[3];
    const float* coefs2 = (const float*)d_in[4];
    float* out = (float*)d_out;

    dim3 grid(NT / COLS_PER_BLOCK, NX / ROWS_PER_BLOCK);  // (8, 128) = 1024 CTAs
    bspline_outer_fused<<<grid, TPB>>>(x, t, knots, coefs, coefs2, out);
}

// round 11
// speedup vs baseline: 1.3629x; 1.0456x over previous
#include <cuda_runtime.h>

// B_Splines fused: out[i][j] = spline(x[i]; coefs) * spline(t[j]; coefs_2)
// degree P=3, N_COEFS=128, knots[132] open-uniform on [0,1], h = 1/125.
//
// FINAL (plateau-locked) config — best of 9 measured variants:
//  - single fused kernel, 64-row x 1024-col tiles, grid = 1024 CTAs
//    (one full resident wave at 8 CTAs/SM, 8192 warps of store concurrency)
//  - SMEM row cache + one barrier (beat shuffle and split-kernel variants)
//  - __stcs STG.128 evict-streaming stores (beat default/-wt/v8 variants;
//    __stwt measured 66us — LTS sector serialization, do not revisit)
//  - division-free Cox-de Boor: open-uniform knots make every denominator
//    n*h, n in {1,2,3}, via integer clamps -> constant-select reciprocal
// In-kernel write rate: 268MB / 45.8us = 5.87 TB/s (~93% of the pure-write
// HBM3e ceiling). Remaining total-vs-kernel gap is graph replay overhead +
// the L2 writeback tail, which is conserved across the replay period.
//
// Inputs (metadata order): x[8192], t[8192], knots[132], coefs[128], coefs_2[128]
// Output: float32 [8192, 8192]

#define NX 8192
#define NT 8192

#define TPB 256
#define ROWS_PER_BLOCK 64
#define COLS_PER_BLOCK (TPB * 4)   // 1024

__device__ __forceinline__ int clampi(int i) {
    return min(max(i, 3), 128);
}

// reciprocal of (n * h), n in {1,2,3}, h = 1/125 (open-uniform closed form)
__device__ __forceinline__ float recip_n(int n) {
    return n == 1 ? 125.0f : (n == 2 ? 62.5f : 41.666668f);
}

__device__ __forceinline__ float rden(int k, int a, int b) {
    return recip_n(clampi(k + a) - clampi(k + b));
}

__device__ __forceinline__ float spline_eval(float xv,
                                             const float* __restrict__ knots,
                                             const float* __restrict__ c) {
    // Knot span: uniform interior gives the guess; local fix against actual
    // fp32 knots keeps indicator parity (t[k] <= x < t[k+1]).
    int k = 3 + (int)floorf(xv * 125.0f);
    k = max(3, min(127, k));
    while (k > 3   && xv <  __ldg(knots + k))     k--;
    while (k < 127 && xv >= __ldg(knots + k + 1)) k++;

    float tm2 = __ldg(knots + k - 2);
    float tm1 = __ldg(knots + k - 1);
    float t0  = __ldg(knots + k);
    float t1  = __ldg(knots + k + 1);
    float t2  = __ldg(knots + k + 2);
    float t3  = __ldg(knots + k + 3);

    float l1 = xv - t0,  r1 = t1 - xv;
    float l2 = xv - tm1, r2 = t2 - xv;
    float l3 = xv - tm2, r3 = t3 - xv;

    // Triangular algorithm (NURBS A2.2), closed-form denominators.
    float N0, N1, N2, N3, temp, saved;
    temp = rden(k, 1, 0);
    N1 = l1 * temp;
    N0 = r1 * temp;
    temp  = N0 * rden(k, 1, -1);
    N0    = r1 * temp;
    saved = l2 * temp;
    temp  = N1 * rden(k, 2, 0);
    N1    = saved + r2 * temp;
    N2    = l1 * temp;
    temp  = N0 * rden(k, 1, -2);
    N0    = r1 * temp;
    saved = l3 * temp;
    temp  = N1 * rden(k, 2, -1);
    N1    = saved + r2 * temp;
    saved = l2 * temp;
    temp  = N2 * rden(k, 3, 0);
    N2    = saved + r3 * temp;
    N3    = l1 * temp;

    return __ldg(c + k - 3) * N0 + __ldg(c + k - 2) * N1 +
           __ldg(c + k - 1) * N2 + __ldg(c + k)     * N3;
}

__global__ __launch_bounds__(TPB, 8) void bspline_outer_fused(
    const float* __restrict__ x,
    const float* __restrict__ t,
    const float* __restrict__ knots,
    const float* __restrict__ coefs,
    const float* __restrict__ coefs2,
    float* __restrict__ out) {
    __shared__ float s_sx[ROWS_PER_BLOCK];

    const int tid = threadIdx.x;
    const int j   = blockIdx.x * COLS_PER_BLOCK + tid * 4;  // base column
    const int r0  = blockIdx.y * ROWS_PER_BLOCK;            // base row

    // Row spline values -> SMEM (threads 0..63).
    if (tid < ROWS_PER_BLOCK) {
        s_sx[tid] = spline_eval(__ldg(x + r0 + tid), knots, coefs);
    }

    // Column spline values for this thread's 4 columns (independent -> ILP).
    float4 tv = *reinterpret_cast<const float4*>(t + j);
    float4 s4;
    s4.x = spline_eval(tv.x, knots, coefs2);
    s4.y = spline_eval(tv.y, knots, coefs2);
    s4.z = spline_eval(tv.z, knots, coefs2);
    s4.w = spline_eval(tv.w, knots, coefs2);

    __syncthreads();

    // Store drain: 64 rows x 16B per thread, fully coalesced, streaming.
    float4* outp = reinterpret_cast<float4*>(out + (size_t)r0 * NT + j);
#pragma unroll 16
    for (int r = 0; r < ROWS_PER_BLOCK; r++) {
        float a = s_sx[r];
        float4 o;
        o.x = a * s4.x;
        o.y = a * s4.y;
        o.z = a * s4.z;
        o.w = a * s4.w;
        __stcs(outp, o);
        outp += NT / 4;
    }
}

extern "C" void kernel_launch(void* const* d_in, const int* in_sizes, int n_in,
                              void* d_out, int out_size) {
    const float* x      = (const float*)d_in[0];
    const float* t      = (const float*)d_in[1];
    const float* knots  = (const float*)d_in[2];
    const float* coefs  = (const float*)d_in[3];
    const float* coefs2 = (const float*)d_in[4];
    float* out = (float*)d_out;

    dim3 grid(NT / COLS_PER_BLOCK, NX / ROWS_PER_BLOCK);  // (8, 128)
    bspline_outer_fused<<<grid, TPB>>>(x, t, knots, coefs, coefs2, out);
}